// round 14
// baseline (speedup 1.0000x reference)
#include <cuda_runtime.h>
#include <float.h>

#define B_  8
#define N_  4096
#define C_  128
#define OI_ 5
#define OS_ 13
#define K_  30
#define FULL 0xffffffffu

// ---- scratch (static device globals; no runtime allocation) ----
__device__ __align__(16) float g_epts[B_ * N_ * 8];            // [b][n][8]: e0..e4, sq, pad
__device__ __align__(16) float g_fsemT[(size_t)B_ * N_ * C_];  // [b][n][c]
__device__ int g_nnidx[B_ * N_ * K_];                          // [b][n][k] (unordered set)

// Order-preserving float <-> u32 key (monotone over the entire float line,
// including negative distances such as rounded self-distances).
__device__ __forceinline__ unsigned f2o(float f) {
    unsigned u = __float_as_uint(f);
    return u ^ ((u & 0x80000000u) ? 0xFFFFFFFFu : 0x80000000u);
}
__device__ __forceinline__ float o2f(unsigned k) {
    k ^= (k & 0x80000000u) ? 0x80000000u : 0xFFFFFFFFu;
    return __uint_as_float(k);
}

// ============================================================================
// Kernel A: fused adaptation MLP + e_ins. (unchanged from passing version)
// ============================================================================
__global__ void __launch_bounds__(256, 1)
mlp_kernel(const float* __restrict__ f_sem, const float* __restrict__ f_ins,
           const float* __restrict__ W_adapt, const float* __restrict__ b_adapt,
           const float* __restrict__ gamma_a, const float* __restrict__ beta_a,
           const float* __restrict__ W_ins, const float* __restrict__ b_ins,
           float* __restrict__ e_out)
{
    extern __shared__ float sm[];
    float* sW   = sm;            // 16384: W_adapt[c][s]
    float* sX   = sm + 16384;    // 16384: f_sem[s][n] tile, then f_sins[c][n]
    float* sWi  = sX + 16384;    // 640:   W_ins[o][c]
    float* sPar = sWi + 640;     // 392:   b_adapt | gamma | beta | b_ins

    const int t  = threadIdx.x;
    const int b  = blockIdx.y;
    const int n0 = blockIdx.x * 128;

    {
        const float4* W4 = (const float4*)W_adapt;
        float4* sW4 = (float4*)sW;
        #pragma unroll
        for (int i = 0; i < 16; i++) sW4[t + 256 * i] = W4[t + 256 * i];
    }
    for (int i4 = t; i4 < 4096; i4 += 256) {
        int s = i4 >> 5, nn = (i4 & 31) * 4;
        ((float4*)sX)[i4] = *(const float4*)(f_sem + ((size_t)(b * C_ + s)) * N_ + n0 + nn);
    }
    if (t < 128) { sPar[t] = b_adapt[t]; sPar[128 + t] = gamma_a[t]; sPar[256 + t] = beta_a[t]; }
    else if (t < 133) sPar[384 + (t - 128)] = b_ins[t - 128];
    for (int i = t; i < 640; i += 256) sWi[i] = W_ins[i];
    __syncthreads();

    const int tx = t & 15, ty = t >> 4;
    const int c0 = ty * 8, nl = tx * 8;
    float acc[8][8];
    #pragma unroll
    for (int u = 0; u < 8; u++)
        #pragma unroll
        for (int v = 0; v < 8; v++) acc[u][v] = 0.f;

    for (int s = 0; s < 128; s++) {
        float a[8];
        #pragma unroll
        for (int u = 0; u < 8; u++) a[u] = sW[(c0 + u) * 128 + s];
        float4 p0 = *(float4*)(sX + s * 128 + nl);
        float4 p1 = *(float4*)(sX + s * 128 + nl + 4);
        float bb[8] = {p0.x, p0.y, p0.z, p0.w, p1.x, p1.y, p1.z, p1.w};
        #pragma unroll
        for (int u = 0; u < 8; u++)
            #pragma unroll
            for (int v = 0; v < 8; v++) acc[u][v] = fmaf(a[u], bb[v], acc[u][v]);
    }
    __syncthreads();  // all reads of sX done before overwrite

    #pragma unroll
    for (int u = 0; u < 8; u++) {
        int c = c0 + u;
        float ba = sPar[c], ga = sPar[128 + c], be = sPar[256 + c];
        const float* fip = f_ins + ((size_t)(b * C_ + c)) * N_ + n0 + nl;
        float4 f0 = *(const float4*)fip;
        float4 f1 = *(const float4*)(fip + 4);
        float fv[8] = {f0.x, f0.y, f0.z, f0.w, f1.x, f1.y, f1.z, f1.w};
        #pragma unroll
        for (int v = 0; v < 8; v++) {
            float val = fmaf(ga, acc[u][v] + ba, be);
            val = fmaxf(val, 0.f) + fv[v];
            sX[c * 128 + nl + v] = val;   // f_sins
        }
    }
    __syncthreads();

    if (t < 128) {
        int n = n0 + t;
        float a0 = sPar[384], a1 = sPar[385], a2 = sPar[386], a3 = sPar[387], a4 = sPar[388];
        for (int c = 0; c < 128; c++) {
            float f = sX[c * 128 + t];
            a0 = fmaf(sWi[c], f, a0);
            a1 = fmaf(sWi[128 + c], f, a1);
            a2 = fmaf(sWi[256 + c], f, a2);
            a3 = fmaf(sWi[384 + c], f, a3);
            a4 = fmaf(sWi[512 + c], f, a4);
        }
        // sq exactly as reference: per-element rounded square, sequential add.
        float s0 = __fmul_rn(a0, a0);
        float s1 = __fmul_rn(a1, a1);
        float s2 = __fmul_rn(a2, a2);
        float s3 = __fmul_rn(a3, a3);
        float s4 = __fmul_rn(a4, a4);
        float sq = __fadd_rn(__fadd_rn(__fadd_rn(__fadd_rn(s0, s1), s2), s3), s4);
        size_t ob = (size_t)b * OI_ * N_ + n;
        e_out[ob] = a0; e_out[ob + N_] = a1; e_out[ob + 2 * N_] = a2;
        e_out[ob + 3 * N_] = a3; e_out[ob + 4 * N_] = a4;
        float* ep = g_epts + ((size_t)b * N_ + n) * 8;
        ep[0] = a0; ep[1] = a1; ep[2] = a2; ep[3] = a3; ep[4] = a4;
        ep[5] = sq; ep[6] = 0.f; ep[7] = 0.f;
    }
}

// ============================================================================
// Kernel B: transpose f_sem [B,C,N] -> g_fsemT [B,N,C]. (unchanged)
// ============================================================================
__global__ void __launch_bounds__(256, 2)
transpose_kernel(const float* __restrict__ f_sem)
{
    __shared__ float tile[32][33];
    const int b = blockIdx.z, c0 = blockIdx.y * 32, x0 = blockIdx.x * 32;
    const int tx = threadIdx.x, ty = threadIdx.y;  // 32 x 8
    #pragma unroll
    for (int j = 0; j < 32; j += 8)
        tile[ty + j][tx] = f_sem[((size_t)(b * C_ + c0 + ty + j)) * N_ + x0 + tx];
    __syncthreads();
    #pragma unroll
    for (int j = 0; j < 32; j += 8)
        g_fsemT[((size_t)b * N_ + x0 + ty + j) * C_ + c0 + tx] = tile[tx][ty + j];
}

// ============================================================================
// Kernel C: exact 30-NN, WARP-PER-QUERY with TWO QUERIES INTERLEAVED.
// The kernel was smem-bandwidth bound (each warp streams the whole 96KB
// candidate array per query). Interleaving two queries in registers lets one
// candidate load (LDS.128 + LDS.64) feed both distance computations, halving
// LDS bytes per query and halving per-query branch overhead. The selection
// machinery per query is IDENTICAL to the passing version: ascending-j strict
// '<' acceptance; branchless insert (predicated replace at evict lane ->
// REDUX.MAX keys -> REDUX.MAX indices among worst-key holders). Distance
// rounding order is bit-identical to the reference.
// ============================================================================
#define KNN_THREADS 1024
#define KNN_WARPS  (KNN_THREADS / 32)
#define QPW 2

__global__ void __launch_bounds__(KNN_THREADS, 2)
knn_kernel()
{
    extern __shared__ float smk[];
    float4* sc4 = (float4*)smk;               // [4096] e0..e3   (64 KB)
    float2* sc2 = (float2*)(smk + 4 * N_);    // [4096] e4, sq   (32 KB)

    const int t = threadIdx.x, b = blockIdx.y;
    {
        const float4* eb = (const float4*)(g_epts + (size_t)b * N_ * 8);
        for (int i = t; i < N_; i += KNN_THREADS) {
            float4 a = eb[2 * i];
            float4 c = eb[2 * i + 1];
            sc4[i] = a;
            sc2[i] = make_float2(c.x, c.y);
        }
    }
    __syncthreads();

    const int w = t >> 5, lane = t & 31;
    const int q0 = (blockIdx.x * KNN_WARPS + w) * QPW;

    const float4 Aq = sc4[q0];
    const float2 Ax = sc2[q0];
    const float4 Bq = sc4[q0 + 1];
    const float2 Bx = sc2[q0 + 1];

    // lane-distributed top-30 per query: lanes >= 30 hold key 0 (below every
    // real key). Sentinel indices distinct per lane & larger than any real j.
    unsigned ka = (lane < K_) ? f2o(FLT_MAX) : 0u;
    unsigned kb = ka;
    int ia = 0x40000000 + lane, ib = ia;
    float wa = FLT_MAX, wb = FLT_MAX;
    int ea = (lane == K_ - 1), eb2 = ea;

    for (int i = 0; i < N_ / 32; i++) {
        const int j = i * 32 + lane;
        float4 cv = sc4[j];
        float2 c2 = sc2[j];

        float dta = __fmul_rn(Aq.x, cv.x);
        float dtb = __fmul_rn(Bq.x, cv.x);
        dta = __fmaf_rn(Aq.y, cv.y, dta);
        dtb = __fmaf_rn(Bq.y, cv.y, dtb);
        dta = __fmaf_rn(Aq.z, cv.z, dta);
        dtb = __fmaf_rn(Bq.z, cv.z, dtb);
        dta = __fmaf_rn(Aq.w, cv.w, dta);
        dtb = __fmaf_rn(Bq.w, cv.w, dtb);
        dta = __fmaf_rn(Ax.x, c2.x, dta);
        dtb = __fmaf_rn(Bx.x, c2.x, dtb);
        float da = __fadd_rn(__fsub_rn(Ax.y, __fmul_rn(2.0f, dta)), c2.y);
        float db = __fadd_rn(__fsub_rn(Bx.y, __fmul_rn(2.0f, dtb)), c2.y);

        unsigned ha = __ballot_sync(FULL, da < wa);
        unsigned hb = __ballot_sync(FULL, db < wb);
        if (ha | hb) {
            while (ha) {
                const int src = __ffs(ha) - 1;
                ha &= ha - 1;
                const float dc = __shfl_sync(FULL, da, src);
                if (dc < wa) {
                    if (ea) { ka = f2o(dc); ia = i * 32 + src; }
                    const unsigned wk = __reduce_max_sync(FULL, ka);
                    const int ik = (ka == wk) ? ia : -1;
                    const int mx = __reduce_max_sync(FULL, ik);
                    ea = (ik == mx);
                    wa = o2f(wk);
                }
            }
            while (hb) {
                const int src = __ffs(hb) - 1;
                hb &= hb - 1;
                const float dc = __shfl_sync(FULL, db, src);
                if (dc < wb) {
                    if (eb2) { kb = f2o(dc); ib = i * 32 + src; }
                    const unsigned wk = __reduce_max_sync(FULL, kb);
                    const int ik = (kb == wk) ? ib : -1;
                    const int mx = __reduce_max_sync(FULL, ik);
                    eb2 = (ik == mx);
                    wb = o2f(wk);
                }
            }
        }
    }

    if (lane < K_) {
        int* op = g_nnidx + ((size_t)b * N_ + q0) * K_;
        op[lane]      = ia;
        op[K_ + lane] = ib;
    }
}

// ============================================================================
// Kernel D: f_isem = max_k f_sem[:, nn_idx[n,k]]; p_sem = W_sem @ f_isem + b.
// (unchanged)
// ============================================================================
__global__ void __launch_bounds__(256, 4)
gather_kernel(const float* __restrict__ W_sem, const float* __restrict__ b_sem,
              float* __restrict__ p_out)
{
    __shared__ __align__(16) float sW[OS_ * C_];
    __shared__ float sb[OS_];
    const int t = threadIdx.x, b = blockIdx.y;
    for (int i = t; i < OS_ * C_; i += 256) sW[i] = W_sem[i];
    if (t < OS_) sb[t] = b_sem[t];
    __syncthreads();

    const int w = t >> 5, lane = t & 31;
    const int n = blockIdx.x * 8 + w;
    const int* ip = g_nnidx + ((size_t)b * N_ + n) * K_;
    int myidx = (lane < K_) ? ip[lane] : 0;
    const float* base = g_fsemT + (size_t)b * N_ * C_;

    float4 m = make_float4(-3.0e38f, -3.0e38f, -3.0e38f, -3.0e38f);
    #pragma unroll
    for (int k = 0; k < K_; k++) {
        int j = __shfl_sync(FULL, myidx, k);
        float4 v = *(const float4*)(base + (size_t)j * C_ + lane * 4);
        m.x = fmaxf(m.x, v.x); m.y = fmaxf(m.y, v.y);
        m.z = fmaxf(m.z, v.z); m.w = fmaxf(m.w, v.w);
    }

    float p[OS_];
    #pragma unroll
    for (int o = 0; o < OS_; o++) {
        float4 wv = *(const float4*)(sW + o * C_ + lane * 4);
        p[o] = m.x * wv.x;
        p[o] = fmaf(m.y, wv.y, p[o]);
        p[o] = fmaf(m.z, wv.z, p[o]);
        p[o] = fmaf(m.w, wv.w, p[o]);
    }
    #pragma unroll
    for (int o = 0; o < OS_; o++)
        #pragma unroll
        for (int off = 16; off; off >>= 1)
            p[o] += __shfl_xor_sync(FULL, p[o], off);

    if (lane == 0) {
        #pragma unroll
        for (int o = 0; o < OS_; o++)
            p_out[((size_t)(b * OS_ + o)) * N_ + n] = p[o] + sb[o];
    }
}

// ============================================================================
extern "C" void kernel_launch(void* const* d_in, const int* in_sizes, int n_in,
                              void* d_out, int out_size)
{
    const float* f_sem   = (const float*)d_in[0];
    const float* f_ins   = (const float*)d_in[1];
    const float* W_adapt = (const float*)d_in[2];
    const float* b_adapt = (const float*)d_in[3];
    const float* gamma_a = (const float*)d_in[4];
    const float* beta_a  = (const float*)d_in[5];
    const float* W_ins   = (const float*)d_in[6];
    const float* b_ins   = (const float*)d_in[7];
    const float* W_sem   = (const float*)d_in[8];
    const float* b_sem   = (const float*)d_in[9];

    float* out   = (float*)d_out;
    float* p_out = out;                           // [B,13,N]
    float* e_out = out + (size_t)B_ * OS_ * N_;   // [B,5,N]

    const int smemA = (16384 + 16384 + 640 + 392) * (int)sizeof(float);  // ~135 KB
    const int smemC = N_ * 6 * (int)sizeof(float);                       // 96 KB
    cudaFuncSetAttribute(mlp_kernel, cudaFuncAttributeMaxDynamicSharedMemorySize, smemA);
    cudaFuncSetAttribute(knn_kernel, cudaFuncAttributeMaxDynamicSharedMemorySize, smemC);

    mlp_kernel<<<dim3(N_ / 128, B_), 256, smemA>>>(
        f_sem, f_ins, W_adapt, b_adapt, gamma_a, beta_a, W_ins, b_ins, e_out);
    transpose_kernel<<<dim3(N_ / 32, C_ / 32, B_), dim3(32, 8)>>>(f_sem);
    knn_kernel<<<dim3(N_ / (KNN_WARPS * QPW), B_), KNN_THREADS, smemC>>>();
    gather_kernel<<<dim3(N_ / 8, B_), 256>>>(W_sem, b_sem, p_out);
}

// round 16
// speedup vs baseline: 1.0556x; 1.0556x over previous
#include <cuda_runtime.h>
#include <float.h>

#define B_  8
#define N_  4096
#define C_  128
#define OI_ 5
#define OS_ 13
#define K_  30
#define FULL 0xffffffffu

// ---- scratch (static device globals; no runtime allocation) ----
__device__ __align__(16) float g_epts[B_ * N_ * 8];            // [b][n][8]: e0..e4, sq, pad
__device__ __align__(16) float g_fsemT[(size_t)B_ * N_ * C_];  // [b][n][c]
__device__ int g_nnidx[B_ * N_ * K_];                          // [b][n][k] (unordered set)

// Order-preserving float <-> u32 key (monotone over the entire float line,
// including negative distances such as rounded self-distances).
__device__ __forceinline__ unsigned f2o(float f) {
    unsigned u = __float_as_uint(f);
    return u ^ ((u & 0x80000000u) ? 0xFFFFFFFFu : 0x80000000u);
}
__device__ __forceinline__ float o2f(unsigned k) {
    k ^= (k & 0x80000000u) ? 0x80000000u : 0xFFFFFFFFu;
    return __uint_as_float(k);
}

// ============================================================================
// Kernel A: fused adaptation MLP + e_ins. (unchanged from passing version)
// ============================================================================
__global__ void __launch_bounds__(256, 1)
mlp_kernel(const float* __restrict__ f_sem, const float* __restrict__ f_ins,
           const float* __restrict__ W_adapt, const float* __restrict__ b_adapt,
           const float* __restrict__ gamma_a, const float* __restrict__ beta_a,
           const float* __restrict__ W_ins, const float* __restrict__ b_ins,
           float* __restrict__ e_out)
{
    extern __shared__ float sm[];
    float* sW   = sm;            // 16384: W_adapt[c][s]
    float* sX   = sm + 16384;    // 16384: f_sem[s][n] tile, then f_sins[c][n]
    float* sWi  = sX + 16384;    // 640:   W_ins[o][c]
    float* sPar = sWi + 640;     // 392:   b_adapt | gamma | beta | b_ins

    const int t  = threadIdx.x;
    const int b  = blockIdx.y;
    const int n0 = blockIdx.x * 128;

    {
        const float4* W4 = (const float4*)W_adapt;
        float4* sW4 = (float4*)sW;
        #pragma unroll
        for (int i = 0; i < 16; i++) sW4[t + 256 * i] = W4[t + 256 * i];
    }
    for (int i4 = t; i4 < 4096; i4 += 256) {
        int s = i4 >> 5, nn = (i4 & 31) * 4;
        ((float4*)sX)[i4] = *(const float4*)(f_sem + ((size_t)(b * C_ + s)) * N_ + n0 + nn);
    }
    if (t < 128) { sPar[t] = b_adapt[t]; sPar[128 + t] = gamma_a[t]; sPar[256 + t] = beta_a[t]; }
    else if (t < 133) sPar[384 + (t - 128)] = b_ins[t - 128];
    for (int i = t; i < 640; i += 256) sWi[i] = W_ins[i];
    __syncthreads();

    const int tx = t & 15, ty = t >> 4;
    const int c0 = ty * 8, nl = tx * 8;
    float acc[8][8];
    #pragma unroll
    for (int u = 0; u < 8; u++)
        #pragma unroll
        for (int v = 0; v < 8; v++) acc[u][v] = 0.f;

    for (int s = 0; s < 128; s++) {
        float a[8];
        #pragma unroll
        for (int u = 0; u < 8; u++) a[u] = sW[(c0 + u) * 128 + s];
        float4 p0 = *(float4*)(sX + s * 128 + nl);
        float4 p1 = *(float4*)(sX + s * 128 + nl + 4);
        float bb[8] = {p0.x, p0.y, p0.z, p0.w, p1.x, p1.y, p1.z, p1.w};
        #pragma unroll
        for (int u = 0; u < 8; u++)
            #pragma unroll
            for (int v = 0; v < 8; v++) acc[u][v] = fmaf(a[u], bb[v], acc[u][v]);
    }
    __syncthreads();  // all reads of sX done before overwrite

    #pragma unroll
    for (int u = 0; u < 8; u++) {
        int c = c0 + u;
        float ba = sPar[c], ga = sPar[128 + c], be = sPar[256 + c];
        const float* fip = f_ins + ((size_t)(b * C_ + c)) * N_ + n0 + nl;
        float4 f0 = *(const float4*)fip;
        float4 f1 = *(const float4*)(fip + 4);
        float fv[8] = {f0.x, f0.y, f0.z, f0.w, f1.x, f1.y, f1.z, f1.w};
        #pragma unroll
        for (int v = 0; v < 8; v++) {
            float val = fmaf(ga, acc[u][v] + ba, be);
            val = fmaxf(val, 0.f) + fv[v];
            sX[c * 128 + nl + v] = val;   // f_sins
        }
    }
    __syncthreads();

    if (t < 128) {
        int n = n0 + t;
        float a0 = sPar[384], a1 = sPar[385], a2 = sPar[386], a3 = sPar[387], a4 = sPar[388];
        for (int c = 0; c < 128; c++) {
            float f = sX[c * 128 + t];
            a0 = fmaf(sWi[c], f, a0);
            a1 = fmaf(sWi[128 + c], f, a1);
            a2 = fmaf(sWi[256 + c], f, a2);
            a3 = fmaf(sWi[384 + c], f, a3);
            a4 = fmaf(sWi[512 + c], f, a4);
        }
        // sq exactly as reference: per-element rounded square, sequential add.
        float s0 = __fmul_rn(a0, a0);
        float s1 = __fmul_rn(a1, a1);
        float s2 = __fmul_rn(a2, a2);
        float s3 = __fmul_rn(a3, a3);
        float s4 = __fmul_rn(a4, a4);
        float sq = __fadd_rn(__fadd_rn(__fadd_rn(__fadd_rn(s0, s1), s2), s3), s4);
        size_t ob = (size_t)b * OI_ * N_ + n;
        e_out[ob] = a0; e_out[ob + N_] = a1; e_out[ob + 2 * N_] = a2;
        e_out[ob + 3 * N_] = a3; e_out[ob + 4 * N_] = a4;
        float* ep = g_epts + ((size_t)b * N_ + n) * 8;
        ep[0] = a0; ep[1] = a1; ep[2] = a2; ep[3] = a3; ep[4] = a4;
        ep[5] = sq; ep[6] = 0.f; ep[7] = 0.f;
    }
}

// ============================================================================
// Kernel B: transpose f_sem [B,C,N] -> g_fsemT [B,N,C]. (unchanged)
// ============================================================================
__global__ void __launch_bounds__(256, 2)
transpose_kernel(const float* __restrict__ f_sem)
{
    __shared__ float tile[32][33];
    const int b = blockIdx.z, c0 = blockIdx.y * 32, x0 = blockIdx.x * 32;
    const int tx = threadIdx.x, ty = threadIdx.y;  // 32 x 8
    #pragma unroll
    for (int j = 0; j < 32; j += 8)
        tile[ty + j][tx] = f_sem[((size_t)(b * C_ + c0 + ty + j)) * N_ + x0 + tx];
    __syncthreads();
    #pragma unroll
    for (int j = 0; j < 32; j += 8)
        g_fsemT[((size_t)b * N_ + x0 + ty + j) * C_ + c0 + tx] = tile[tx][ty + j];
}

// ============================================================================
// Kernel C: exact 30-NN, WARP-PER-QUERY (single query per warp, as in the
// 359us version), with the candidate scan UNROLLED x2 under a COMBINED
// ballot: one ballot((d0<worst)|(d1<worst)) covers 64 candidates; the two
// precise sub-ballots are issued only when at least one lane hits (rare after
// warm-up). Group A (j in [64i,64i+32)) is processed before group B and
// ascending src within each group, so global candidate order stays ascending
// j -> strict '<' tie semantics identical. Sub-ballots use the pre-insert
// 'worst' but every insert re-checks dc<worst against the tightened value
// (same pattern as the passing version). Branchless insert: predicated
// replace at evict lane -> REDUX.MAX keys -> REDUX.MAX indices among
// worst-key holders. Distance rounding order bit-identical to the reference.
// ============================================================================
#define KNN_THREADS 1024
#define KNN_WARPS  (KNN_THREADS / 32)

__global__ void __launch_bounds__(KNN_THREADS, 2)
knn_kernel()
{
    extern __shared__ float smk[];
    float4* sc4 = (float4*)smk;               // [4096] e0..e3   (64 KB)
    float2* sc2 = (float2*)(smk + 4 * N_);    // [4096] e4, sq   (32 KB)

    const int t = threadIdx.x, b = blockIdx.y;
    {
        const float4* eb = (const float4*)(g_epts + (size_t)b * N_ * 8);
        for (int i = t; i < N_; i += KNN_THREADS) {
            float4 a = eb[2 * i];
            float4 c = eb[2 * i + 1];
            sc4[i] = a;
            sc2[i] = make_float2(c.x, c.y);
        }
    }
    __syncthreads();

    const int w = t >> 5, lane = t & 31;
    const int q = blockIdx.x * KNN_WARPS + w;

    float4 qa = sc4[q];
    float2 qb = sc2[q];
    const float e0 = qa.x, e1 = qa.y, e2 = qa.z, e3 = qa.w;
    const float e4 = qb.x, sqi = qb.y;

    // lane-distributed top-30: lanes >= 30 hold key 0 (below every real key).
    // Sentinel indices distinct per lane and larger than any real j.
    unsigned bdk = (lane < K_) ? f2o(FLT_MAX) : 0u;
    int bi = 0x40000000 + lane;
    float worst = FLT_MAX;
    int ev = (lane == K_ - 1);

    for (int i = 0; i < N_ / 64; i++) {
        const int base = i * 64;
        // candidate A: j = base + lane
        float4 cv0 = sc4[base + lane];
        float2 c20 = sc2[base + lane];
        float dot0 = __fmul_rn(e0, cv0.x);
        dot0 = __fmaf_rn(e1, cv0.y, dot0);
        dot0 = __fmaf_rn(e2, cv0.z, dot0);
        dot0 = __fmaf_rn(e3, cv0.w, dot0);
        dot0 = __fmaf_rn(e4, c20.x, dot0);
        float d0 = __fadd_rn(__fsub_rn(sqi, __fmul_rn(2.0f, dot0)), c20.y);
        // candidate B: j = base + 32 + lane
        float4 cv1 = sc4[base + 32 + lane];
        float2 c21 = sc2[base + 32 + lane];
        float dot1 = __fmul_rn(e0, cv1.x);
        dot1 = __fmaf_rn(e1, cv1.y, dot1);
        dot1 = __fmaf_rn(e2, cv1.z, dot1);
        dot1 = __fmaf_rn(e3, cv1.w, dot1);
        dot1 = __fmaf_rn(e4, c21.x, dot1);
        float d1 = __fadd_rn(__fsub_rn(sqi, __fmul_rn(2.0f, dot1)), c21.y);

        unsigned any = __ballot_sync(FULL, (d0 < worst) | (d1 < worst));
        if (any) {
            unsigned ha = __ballot_sync(FULL, d0 < worst);
            unsigned hb = __ballot_sync(FULL, d1 < worst);
            while (ha) {
                const int src = __ffs(ha) - 1;
                ha &= ha - 1;
                const float dc = __shfl_sync(FULL, d0, src);
                if (dc < worst) {
                    if (ev) { bdk = f2o(dc); bi = base + src; }
                    const unsigned wk = __reduce_max_sync(FULL, bdk);
                    const int ik = (bdk == wk) ? bi : -1;
                    const int mx = __reduce_max_sync(FULL, ik);
                    ev = (ik == mx);
                    worst = o2f(wk);
                }
            }
            while (hb) {
                const int src = __ffs(hb) - 1;
                hb &= hb - 1;
                const float dc = __shfl_sync(FULL, d1, src);
                if (dc < worst) {
                    if (ev) { bdk = f2o(dc); bi = base + 32 + src; }
                    const unsigned wk = __reduce_max_sync(FULL, bdk);
                    const int ik = (bdk == wk) ? bi : -1;
                    const int mx = __reduce_max_sync(FULL, ik);
                    ev = (ik == mx);
                    worst = o2f(wk);
                }
            }
        }
    }

    if (lane < K_)
        g_nnidx[((size_t)b * N_ + q) * K_ + lane] = bi;
}

// ============================================================================
// Kernel D: f_isem = max_k f_sem[:, nn_idx[n,k]]; p_sem = W_sem @ f_isem + b.
// (unchanged)
// ============================================================================
__global__ void __launch_bounds__(256, 4)
gather_kernel(const float* __restrict__ W_sem, const float* __restrict__ b_sem,
              float* __restrict__ p_out)
{
    __shared__ __align__(16) float sW[OS_ * C_];
    __shared__ float sb[OS_];
    const int t = threadIdx.x, b = blockIdx.y;
    for (int i = t; i < OS_ * C_; i += 256) sW[i] = W_sem[i];
    if (t < OS_) sb[t] = b_sem[t];
    __syncthreads();

    const int w = t >> 5, lane = t & 31;
    const int n = blockIdx.x * 8 + w;
    const int* ip = g_nnidx + ((size_t)b * N_ + n) * K_;
    int myidx = (lane < K_) ? ip[lane] : 0;
    const float* base = g_fsemT + (size_t)b * N_ * C_;

    float4 m = make_float4(-3.0e38f, -3.0e38f, -3.0e38f, -3.0e38f);
    #pragma unroll
    for (int k = 0; k < K_; k++) {
        int j = __shfl_sync(FULL, myidx, k);
        float4 v = *(const float4*)(base + (size_t)j * C_ + lane * 4);
        m.x = fmaxf(m.x, v.x); m.y = fmaxf(m.y, v.y);
        m.z = fmaxf(m.z, v.z); m.w = fmaxf(m.w, v.w);
    }

    float p[OS_];
    #pragma unroll
    for (int o = 0; o < OS_; o++) {
        float4 wv = *(const float4*)(sW + o * C_ + lane * 4);
        p[o] = m.x * wv.x;
        p[o] = fmaf(m.y, wv.y, p[o]);
        p[o] = fmaf(m.z, wv.z, p[o]);
        p[o] = fmaf(m.w, wv.w, p[o]);
    }
    #pragma unroll
    for (int o = 0; o < OS_; o++)
        #pragma unroll
        for (int off = 16; off; off >>= 1)
            p[o] += __shfl_xor_sync(FULL, p[o], off);

    if (lane == 0) {
        #pragma unroll
        for (int o = 0; o < OS_; o++)
            p_out[((size_t)(b * OS_ + o)) * N_ + n] = p[o] + sb[o];
    }
}

// ============================================================================
extern "C" void kernel_launch(void* const* d_in, const int* in_sizes, int n_in,
                              void* d_out, int out_size)
{
    const float* f_sem   = (const float*)d_in[0];
    const float* f_ins   = (const float*)d_in[1];
    const float* W_adapt = (const float*)d_in[2];
    const float* b_adapt = (const float*)d_in[3];
    const float* gamma_a = (const float*)d_in[4];
    const float* beta_a  = (const float*)d_in[5];
    const float* W_ins   = (const float*)d_in[6];
    const float* b_ins   = (const float*)d_in[7];
    const float* W_sem   = (const float*)d_in[8];
    const float* b_sem   = (const float*)d_in[9];

    float* out   = (float*)d_out;
    float* p_out = out;                           // [B,13,N]
    float* e_out = out + (size_t)B_ * OS_ * N_;   // [B,5,N]

    const int smemA = (16384 + 16384 + 640 + 392) * (int)sizeof(float);  // ~135 KB
    const int smemC = N_ * 6 * (int)sizeof(float);                       // 96 KB
    cudaFuncSetAttribute(mlp_kernel, cudaFuncAttributeMaxDynamicSharedMemorySize, smemA);
    cudaFuncSetAttribute(knn_kernel, cudaFuncAttributeMaxDynamicSharedMemorySize, smemC);

    mlp_kernel<<<dim3(N_ / 128, B_), 256, smemA>>>(
        f_sem, f_ins, W_adapt, b_adapt, gamma_a, beta_a, W_ins, b_ins, e_out);
    transpose_kernel<<<dim3(N_ / 32, C_ / 32, B_), dim3(32, 8)>>>(f_sem);
    knn_kernel<<<dim3(N_ / KNN_WARPS, B_), KNN_THREADS, smemC>>>();
    gather_kernel<<<dim3(N_ / 8, B_), 256>>>(W_sem, b_sem, p_out);
}